// round 13
// baseline (speedup 1.0000x reference)
#include <cuda_runtime.h>
#include <cuda_fp16.h>
#include <math_constants.h>
#include <cstdint>

#define Ssz  50
#define NPT  3200
#define NROW 9600
#define ERT  160000
#define NB   1280

#define RSCALE   2048.0f          // residual scale 2^11
#define RINV     (1.0f/2048.0f)

// ================= static device scratch (no allocation) =================
static __device__ __half g_es0[(size_t)480000*256], g_es1[(size_t)480000*256];
static __device__ float g_gx0[(size_t)ERT*1024], g_gx1[(size_t)ERT*1024], g_gx2[(size_t)ERT*1024];
static __device__ float g_et0[(size_t)ERT*256],  g_et1[(size_t)ERT*256],  g_et2[(size_t)ERT*256];
static __device__ __half g_h0s[NROW*256], g_h1s[NROW*256];
static __device__ float g_c[NROW*256];
static __device__ float g_graw[(size_t)NROW*1024];
static __device__ float g_dec[(size_t)NROW*256];
static __device__ __half g_bs0[NB*256], g_bs1[NB*256];   // [Whh;W2] splits
static __device__ __half g_bp0[NB*256], g_bp1[NB*256];   // [Wih;W1] splits
static __device__ float g_bias[1024];

__device__ __forceinline__ float* gx_ptr(int t){ return (t==0)?g_gx0:((t==1)?g_gx1:g_gx2); }
__device__ __forceinline__ float* et_ptr(int t){ return (t==0)?g_et0:((t==1)?g_et1:g_et2); }
__device__ __forceinline__ void split2(float v, __half& a, __half& b){
    a = __float2half_rn(v);
    float r = v - __half2float(a);
    b = __float2half_rn(r * RSCALE);
}
__device__ __forceinline__ float fsig(float x){ return __fdividef(1.f, 1.f + __expf(-x)); }
__device__ __forceinline__ float ftanh(float x){ return 1.f - __fdividef(2.f, 1.f + __expf(2.f*x)); }

// ================= baseline-PTX tensor helpers =================
__device__ __forceinline__ uint32_t smem_u32(const void* p){
    uint32_t a;
    asm("{ .reg .u64 t; cvta.to.shared.u64 t, %1; cvt.u32.u64 %0, t; }" : "=r"(a) : "l"(p));
    return a;
}
__device__ __forceinline__ void ldsm4(uint32_t* r, uint32_t addr){
    asm volatile("ldmatrix.sync.aligned.m8n8.x4.shared.b16 {%0,%1,%2,%3}, [%4];"
        : "=r"(r[0]), "=r"(r[1]), "=r"(r[2]), "=r"(r[3]) : "r"(addr));
}
__device__ __forceinline__ void mma16816(float* c, const uint32_t* a, const uint32_t* b){
    asm volatile("mma.sync.aligned.m16n8k16.row.col.f32.f16.f16.f32 "
        "{%0,%1,%2,%3}, {%4,%5,%6,%7}, {%8,%9}, {%0,%1,%2,%3};"
        : "+f"(c[0]), "+f"(c[1]), "+f"(c[2]), "+f"(c[3])
        : "r"(a[0]), "r"(a[1]), "r"(a[2]), "r"(a[3]), "r"(b[0]), "r"(b[1]));
}
__device__ __forceinline__ void cpa16(uint32_t d, const void* s){
    asm volatile("cp.async.cg.shared.global [%0], [%1], 16;" :: "r"(d), "l"(s));
}
#define CP_COMMIT() asm volatile("cp.async.commit_group;" ::: "memory")
#define CP_WAIT0()  asm volatile("cp.async.wait_group 0;" ::: "memory")
#define CP_WAIT1()  asm volatile("cp.async.wait_group 1;" ::: "memory")
#define CP_WAIT2()  asm volatile("cp.async.wait_group 2;" ::: "memory")

// ================= prep kernels =================
__global__ void pack_b_kernel(const float* __restrict__ Whh, const float* __restrict__ W2,
                              const float* __restrict__ Wih, const float* __restrict__ W1,
                              const float* __restrict__ bih, const float* __restrict__ bhh){
    int row = blockIdx.x, k = threadIdx.x, j = row*256 + k;
    float ws = (row < 1024) ? Whh[j] : W2[(size_t)(row-1024)*256 + k];
    float wp = (row < 1024) ? Wih[j] : W1[(size_t)(row-1024)*256 + k];
    split2(ws, g_bs0[j], g_bs1[j]);
    split2(wp, g_bp0[j], g_bp1[j]);
    if (row < 4) g_bias[j] = bih[j] + bhh[j];
}

// fused: split enc rows AND compute h0 = c0 = sum_s enc (enc read once)
__global__ void prep_kernel(const float* __restrict__ e0, const float* __restrict__ e1,
                            const float* __restrict__ e2){
    int r = blockIdx.x;                       // 0..9599
    int k = threadIdx.x;
    int t = r / NPT, n = r % NPT;
    const float* e = ((t==0)?e0:((t==1)?e1:e2)) + (size_t)n*(Ssz*256) + k;
    size_t wbase = ((size_t)t*ERT + (size_t)n*Ssz)*256 + k;
    float s = 0.f;
#pragma unroll 1
    for (int ss = 0; ss < Ssz; ss++){
        float v = e[ss*256];
        s += v;
        split2(v, g_es0[wbase + (size_t)ss*256], g_es1[wbase + (size_t)ss*256]);
    }
    g_c[r*256+k] = s;
    split2(s, g_h0s[r*256+k], g_h1s[r*256+k]);
}

// ================= emulated-fp32 GEMM via mma.sync fp16 (2-way split, 3 products) =================
// CTA tile 128x64, warp tile 32x32 (4x2 warps), 2 CTAs/SM.
// 3-stage cp.async pipeline over 8 K-chunks of 32.
// grid.x = n-block (fast -> co-resident CTAs share the A tile in L2), grid.y = m-block.
#define NCH    8
#define ASTR2  40                     // halfs per tile row (80 B; conflict-free ldsm)
#define ATIL2  (128*ASTR2*2)          // 10240 B
#define BTIL2  (64*ASTR2*2)           // 5120 B
#define STG2   (2*ATIL2 + 2*BTIL2)    // 30720 B : A0 A1 B0 B1
#define GSMEM  (3*STG2)               // 92160 B

__global__ __launch_bounds__(256, 2) void gemm_kernel(
    const __half* __restrict__ A0, const __half* __restrict__ A1,
    const __half* __restrict__ B0, const __half* __restrict__ B1,
    float* __restrict__ Cg, float* __restrict__ Cd)
{
    extern __shared__ __half sh[];
    uint32_t sb = smem_u32(sh);

    const int tid = threadIdx.x, lane = tid & 31, w = tid >> 5;
    const int wm = w & 3, wn = w >> 2;
    const size_t m0 = (size_t)blockIdx.y * 128;
    const int n0 = blockIdx.x * 64;

    float acc0[2][4][4], acc1[2][4][4];
#pragma unroll
    for (int i = 0; i < 2; i++)
#pragma unroll
        for (int j = 0; j < 4; j++)
#pragma unroll
            for (int q = 0; q < 4; q++){ acc0[i][j][q] = 0.f; acc1[i][j][q] = 0.f; }

    const __half* Asrc[2] = { A0 + m0*256, A1 + m0*256 };
    const __half* Bsrc[2] = { B0 + (size_t)n0*256, B1 + (size_t)n0*256 };

    const int arow = wm*32 + (lane & 15);
    const int akof = (lane >> 4) * 8;
    const int brow = wn*32 + (lane & 7) + ((lane >> 4) << 3);
    const int bkof = ((lane >> 3) & 1) * 8;

    // per-thread copy coords: A has 512 16B segs/split (4 per row), B has 256 (4 per row)
    const int ar0 = tid >> 2, aseg = tid & 3;      // + i*64 rows for i in {0,1}

    auto load_stage = [&](int c){
        uint32_t base = sb + (uint32_t)(c % 3)*STG2;
        const int coff = c*32;
#pragma unroll
        for (int t = 0; t < 2; t++){
            const __half* src = Asrc[t] + coff;
#pragma unroll
            for (int i = 0; i < 2; i++){
                int row = ar0 + i*64;
                cpa16(base + t*ATIL2 + (uint32_t)(row*ASTR2 + aseg*8)*2,
                      src + (size_t)row*256 + aseg*8);
            }
        }
#pragma unroll
        for (int t = 0; t < 2; t++){
            const __half* src = Bsrc[t] + coff;
            cpa16(base + 2*ATIL2 + t*BTIL2 + (uint32_t)(ar0*ASTR2 + aseg*8)*2,
                  src + (size_t)ar0*256 + aseg*8);
        }
        CP_COMMIT();
    };

    load_stage(0);
    load_stage(1);
#pragma unroll 1
    for (int c = 0; c < NCH; c++){
        if (c + 2 < NCH){ load_stage(c + 2); CP_WAIT2(); }
        else if (c + 1 < NCH){ CP_WAIT1(); }
        else CP_WAIT0();
        __syncthreads();
        uint32_t base = sb + (uint32_t)(c % 3)*STG2;
        uint32_t a0b = base, a1b = base + ATIL2;
        uint32_t b0b = base + 2*ATIL2, b1b = b0b + BTIL2;
#pragma unroll
        for (int ks = 0; ks < 2; ks++){
            uint32_t b0f[4][2], b1f[4][2];
#pragma unroll
            for (int f2 = 0; f2 < 2; f2++){
                uint32_t off = (uint32_t)((brow + f2*16)*ASTR2 + ks*16 + bkof)*2;
                uint32_t r[4];
                ldsm4(r, b0b + off);
                b0f[f2*2][0] = r[0]; b0f[f2*2][1] = r[1];
                b0f[f2*2+1][0] = r[2]; b0f[f2*2+1][1] = r[3];
                ldsm4(r, b1b + off);
                b1f[f2*2][0] = r[0]; b1f[f2*2][1] = r[1];
                b1f[f2*2+1][0] = r[2]; b1f[f2*2+1][1] = r[3];
            }
#pragma unroll
            for (int fm = 0; fm < 2; fm++){
                uint32_t aoff = (uint32_t)((arow + fm*16)*ASTR2 + ks*16 + akof)*2;
                uint32_t a0f[4], a1f[4];
                ldsm4(a0f, a0b + aoff);
                ldsm4(a1f, a1b + aoff);
#pragma unroll
                for (int fn = 0; fn < 4; fn++){
                    mma16816(acc0[fm][fn], a0f, b0f[fn]);
                    mma16816(acc1[fm][fn], a0f, b1f[fn]);
                    mma16816(acc1[fm][fn], a1f, b0f[fn]);
                }
            }
        }
        __syncthreads();
    }

    // epilogue: route n<1024 -> Cg (w=1024), n>=1024 -> Cd (w=256)
    const bool isg = (n0 < 1024);
    float* Cb = isg ? Cg : Cd;
    const int cw = isg ? 1024 : 256;
    const int col = (isg ? n0 : (n0 - 1024)) + wn*32 + 2*(lane & 3);
#pragma unroll
    for (int fm = 0; fm < 2; fm++){
        size_t mrow = m0 + wm*32 + fm*16 + (lane >> 2);
        float* cp0 = Cb + mrow*cw     + col;
        float* cp1 = Cb + (mrow+8)*cw + col;
#pragma unroll
        for (int fn = 0; fn < 4; fn++){
            *(float2*)(cp0 + fn*8) = make_float2(fmaf(acc1[fm][fn][0], RINV, acc0[fm][fn][0]),
                                                 fmaf(acc1[fm][fn][1], RINV, acc0[fm][fn][1]));
            *(float2*)(cp1 + fn*8) = make_float2(fmaf(acc1[fm][fn][2], RINV, acc0[fm][fn][2]),
                                                 fmaf(acc1[fm][fn][3], RINV, acc0[fm][fn][3]));
        }
    }
}

// ================= cell0: initial cell (x=0, no gather) =================
__global__ __launch_bounds__(256) void cell0_kernel(){
    int k = threadIdx.x;
#pragma unroll
    for (int rr = 0; rr < 4; rr++){
        int r = blockIdx.x*4 + rr;
        const float* g = g_graw + (size_t)r*1024;
        float i = fsig (g[k]     + g_bias[k]);
        float f = fsig (g[256+k] + g_bias[256+k]);
        float gv= ftanh(g[512+k] + g_bias[512+k]);
        float o = fsig (g[768+k] + g_bias[768+k]);
        float cn = fmaf(f, g_c[r*256+k], i*gv);
        g_c[r*256+k] = cn;
        split2(o * ftanh(cn), g_h0s[r*256+k], g_h1s[r*256+k]);
    }
}

// per-s attention dot: u contribution of one s row (identical math/order to prior rounds)
__device__ __forceinline__ float attn_dot(float4 e0, float4 e1,
                                          const float* dec_s, const float* vt_s, int lane){
    float4 d0 = *(const float4*)(&dec_s[4*lane]);
    float4 d1 = *(const float4*)(&dec_s[128 + 4*lane]);
    float4 v0 = *(const float4*)(&vt_s[4*lane]);
    float4 v1 = *(const float4*)(&vt_s[128 + 4*lane]);
    float p0 = ftanh(e0.x + d0.x) * v0.x;
    float p1 = ftanh(e0.y + d0.y) * v0.y;
    p0 = fmaf(ftanh(e0.z + d0.z), v0.z, p0);
    p1 = fmaf(ftanh(e0.w + d0.w), v0.w, p1);
    p0 = fmaf(ftanh(e1.x + d1.x), v1.x, p0);
    p1 = fmaf(ftanh(e1.y + d1.y), v1.y, p1);
    p0 = fmaf(ftanh(e1.z + d1.z), v1.z, p0);
    p1 = fmaf(ftanh(e1.w + d1.w), v1.w, p1);
    return p0 + p1;
}
__device__ __forceinline__ float wredu(float p){
#pragma unroll
    for (int off = 16; off; off >>= 1) p += __shfl_xor_sync(0xffffffffu, p, off);
    return p;
}

// ================= fused attention(step) + cell(step+1) =================
__global__ __launch_bounds__(256) void attn_cell_kernel(int step, int do_cell,
                                                        const float* __restrict__ vt,
                                                        float* __restrict__ out){
    __shared__ float dec_s[256], vt_s[256], u_s[Ssz];
    __shared__ int idx_sh;
    int tid = threadIdx.x, wid = tid >> 5, lane = tid & 31;
    int r = blockIdx.x;                       // global row 0..9599
    int t = r / NPT, n = r % NPT;
    dec_s[tid] = g_dec[(size_t)r*256 + tid];
    vt_s[tid]  = vt[tid];
    __syncthreads();

    const float* eb = et_ptr(t) + (size_t)n*Ssz*256;   // fully contiguous 51.2 KB
    // warp owns s = wid + {0,8,16,24,32,40}; all 12 row-halves loaded up-front (max MLP)
    {
        float4 e[6][2];
#pragma unroll
        for (int j = 0; j < 6; j++){
            const float4* ep = (const float4*)(eb + (size_t)(wid + j*8)*256);
            e[j][0] = ep[lane];
            e[j][1] = ep[32 + lane];
        }
        float p[6];
#pragma unroll
        for (int j = 0; j < 6; j++) p[j] = attn_dot(e[j][0], e[j][1], dec_s, vt_s, lane);
#pragma unroll
        for (int j = 0; j < 6; j++){
            float q = wredu(p[j]);
            if (lane == 0) u_s[wid + j*8] = q;
        }
    }
    if (wid < 2){
        int s = 48 + wid;
        const float4* ep = (const float4*)(eb + (size_t)s*256);
        float4 e0 = ep[lane], e1 = ep[32 + lane];
        float q = wredu(attn_dot(e0, e1, dec_s, vt_s, lane));
        if (lane == 0) u_s[s] = q;
    }
    __syncthreads();

    if (wid == 0){
        float ua = u_s[lane];
        float ub = (lane + 32 < Ssz) ? u_s[lane + 32] : -CUDART_INF_F;
        float bm = ua; int bi = lane;
        if (ub > bm){ bm = ub; bi = lane + 32; }
#pragma unroll
        for (int off = 16; off; off >>= 1){
            float vm = __shfl_xor_sync(0xffffffffu, bm, off);
            int   vi = __shfl_xor_sync(0xffffffffu, bi, off);
            if (vm > bm || (vm == bm && vi < bi)){ bm = vm; bi = vi; }
        }
        float ea = __expf(ua - bm);
        float eb2 = (lane + 32 < Ssz) ? __expf(ub - bm) : 0.f;
        float sm = ea + eb2;
#pragma unroll
        for (int off = 16; off; off >>= 1) sm += __shfl_xor_sync(0xffffffffu, sm, off);
        float inv = 1.0f / sm;
        float* so = out + (size_t)t*8160000 + (size_t)n*2500 + step*50;
        so[lane] = ea * inv;
        if (lane + 32 < Ssz) so[lane + 32] = eb2 * inv;
        if (lane == 0){
            idx_sh = bi;
            out[(size_t)t*8160000 + 8000000 + (size_t)n*50 + step] = (float)bi;
        }
    }
    __syncthreads();

    if (do_cell){
        int k = tid;
        const float* g = g_graw + (size_t)r*1024;
        const float* ex = gx_ptr(t) + (size_t)(n*Ssz + idx_sh)*1024;
        float i = fsig (g[k]     + ex[k]     + g_bias[k]);
        float f = fsig (g[256+k] + ex[256+k] + g_bias[256+k]);
        float gv= ftanh(g[512+k] + ex[512+k] + g_bias[512+k]);
        float o = fsig (g[768+k] + ex[768+k] + g_bias[768+k]);
        float cn = fmaf(f, g_c[r*256+k], i*gv);
        g_c[r*256+k] = cn;
        split2(o * ftanh(cn), g_h0s[r*256+k], g_h1s[r*256+k]);
    }
}

// ================= launch =================
extern "C" void kernel_launch(void* const* d_in, const int* in_sizes, int n_in,
                              void* d_out, int out_size){
    const float* home = (const float*)d_in[0];
    const float* vis  = (const float*)d_in[1];
    const float* team = (const float*)d_in[2];
    const float* Wih  = (const float*)d_in[3];
    const float* Whh  = (const float*)d_in[4];
    const float* bih  = (const float*)d_in[5];
    const float* bhh  = (const float*)d_in[6];
    const float* W1   = (const float*)d_in[7];
    const float* W2   = (const float*)d_in[8];
    const float* vt   = (const float*)d_in[9];
    float* out = (float*)d_out;

    cudaFuncSetAttribute(gemm_kernel, cudaFuncAttributeMaxDynamicSharedMemorySize, GSMEM);

    pack_b_kernel<<<NB, 256>>>(Whh, W2, Wih, W1, bih, bhh);
    prep_kernel<<<NROW, 256>>>(home, vis, team);

    __half *es0, *es1, *bp0, *bp1, *bs0, *bs1, *h0, *h1;
    float *gx0, *gx1, *gx2, *et0, *et1, *et2, *graw, *dec;
    cudaGetSymbolAddress((void**)&es0, g_es0);  cudaGetSymbolAddress((void**)&es1, g_es1);
    cudaGetSymbolAddress((void**)&bp0, g_bp0);  cudaGetSymbolAddress((void**)&bp1, g_bp1);
    cudaGetSymbolAddress((void**)&bs0, g_bs0);  cudaGetSymbolAddress((void**)&bs1, g_bs1);
    cudaGetSymbolAddress((void**)&h0,  g_h0s);  cudaGetSymbolAddress((void**)&h1,  g_h1s);
    cudaGetSymbolAddress((void**)&gx0, g_gx0);  cudaGetSymbolAddress((void**)&gx1, g_gx1);
    cudaGetSymbolAddress((void**)&gx2, g_gx2);
    cudaGetSymbolAddress((void**)&et0, g_et0);  cudaGetSymbolAddress((void**)&et1, g_et1);
    cudaGetSymbolAddress((void**)&et2, g_et2);
    cudaGetSymbolAddress((void**)&graw, g_graw); cudaGetSymbolAddress((void**)&dec, g_dec);

    float* gxs[3] = {gx0, gx1, gx2};
    float* ets[3] = {et0, et1, et2};
    for (int t = 0; t < 3; t++){
        size_t off = (size_t)t * ERT * 256;
        gemm_kernel<<<dim3(20, 1250), 256, GSMEM>>>(es0 + off, es1 + off, bp0, bp1,
                                                    gxs[t], ets[t]);
    }

    // bootstrap: gates from h0 -> cell0 -> gates+dec
    gemm_kernel<<<dim3(20, 75), 256, GSMEM>>>(h0, h1, bs0, bs1, graw, dec);
    cell0_kernel<<<NROW/4, 256>>>();
    gemm_kernel<<<dim3(20, 75), 256, GSMEM>>>(h0, h1, bs0, bs1, graw, dec);

    for (int i = 0; i < Ssz; i++){
        attn_cell_kernel<<<NROW, 256>>>(i, (i + 1 < Ssz) ? 1 : 0, vt, out);
        if (i + 1 < Ssz)
            gemm_kernel<<<dim3(20, 75), 256, GSMEM>>>(h0, h1, bs0, bs1, graw, dec);
    }
}

// round 15
// speedup vs baseline: 1.0815x; 1.0815x over previous
#include <cuda_runtime.h>
#include <cuda_fp16.h>
#include <math_constants.h>
#include <cstdint>

#define Ssz  50
#define NPT  3200
#define NROW 9600
#define ERT  160000
#define NB   1280

#define RSCALE   2048.0f          // residual scale 2^11
#define RINV     (1.0f/2048.0f)

// ================= static device scratch (no allocation) =================
static __device__ __half g_es0[(size_t)480000*256], g_es1[(size_t)480000*256];
static __device__ float g_gx0[(size_t)ERT*1024], g_gx1[(size_t)ERT*1024], g_gx2[(size_t)ERT*1024];
static __device__ float g_et0[(size_t)ERT*256],  g_et1[(size_t)ERT*256],  g_et2[(size_t)ERT*256];
static __device__ __half g_h0s[NROW*256], g_h1s[NROW*256];
static __device__ float g_c[NROW*256];
static __device__ float g_graw[(size_t)NROW*1024];
static __device__ float g_dec[(size_t)NROW*256];
static __device__ __half g_bs0[NB*256], g_bs1[NB*256];   // [Whh;W2] splits
static __device__ __half g_bp0[NB*256], g_bp1[NB*256];   // [Wih;W1] splits
static __device__ float g_bias[1024];
static __device__ float g_delta;                          // certified argmax margin

__device__ __forceinline__ float* gx_ptr(int t){ return (t==0)?g_gx0:((t==1)?g_gx1:g_gx2); }
__device__ __forceinline__ float* et_ptr(int t){ return (t==0)?g_et0:((t==1)?g_et1:g_et2); }
__device__ __forceinline__ void split2(float v, __half& a, __half& b){
    a = __float2half_rn(v);
    float r = v - __half2float(a);
    b = __float2half_rn(r * RSCALE);
}
__device__ __forceinline__ float fsig(float x){ return __fdividef(1.f, 1.f + __expf(-x)); }
__device__ __forceinline__ float ftanh(float x){ return 1.f - __fdividef(2.f, 1.f + __expf(2.f*x)); }
__device__ __forceinline__ float htanh(float x){
    float y;
    asm("tanh.approx.f32 %0, %1;" : "=f"(y) : "f"(x));
    return y;
}

// ================= baseline-PTX tensor helpers =================
__device__ __forceinline__ uint32_t smem_u32(const void* p){
    uint32_t a;
    asm("{ .reg .u64 t; cvta.to.shared.u64 t, %1; cvt.u32.u64 %0, t; }" : "=r"(a) : "l"(p));
    return a;
}
__device__ __forceinline__ void ldsm4(uint32_t* r, uint32_t addr){
    asm volatile("ldmatrix.sync.aligned.m8n8.x4.shared.b16 {%0,%1,%2,%3}, [%4];"
        : "=r"(r[0]), "=r"(r[1]), "=r"(r[2]), "=r"(r[3]) : "r"(addr));
}
__device__ __forceinline__ void mma16816(float* c, const uint32_t* a, const uint32_t* b){
    asm volatile("mma.sync.aligned.m16n8k16.row.col.f32.f16.f16.f32 "
        "{%0,%1,%2,%3}, {%4,%5,%6,%7}, {%8,%9}, {%0,%1,%2,%3};"
        : "+f"(c[0]), "+f"(c[1]), "+f"(c[2]), "+f"(c[3])
        : "r"(a[0]), "r"(a[1]), "r"(a[2]), "r"(a[3]), "r"(b[0]), "r"(b[1]));
}
__device__ __forceinline__ void cpa16(uint32_t d, const void* s){
    asm volatile("cp.async.cg.shared.global [%0], [%1], 16;" :: "r"(d), "l"(s));
}
#define CP_COMMIT() asm volatile("cp.async.commit_group;" ::: "memory")
#define CP_WAIT0()  asm volatile("cp.async.wait_group 0;" ::: "memory")
#define CP_WAIT1()  asm volatile("cp.async.wait_group 1;" ::: "memory")

// ================= prep kernels =================
__global__ void pack_b_kernel(const float* __restrict__ Whh, const float* __restrict__ W2,
                              const float* __restrict__ Wih, const float* __restrict__ W1,
                              const float* __restrict__ bih, const float* __restrict__ bhh){
    int row = blockIdx.x, k = threadIdx.x, j = row*256 + k;
    float ws = (row < 1024) ? Whh[j] : W2[(size_t)(row-1024)*256 + k];
    float wp = (row < 1024) ? Wih[j] : W1[(size_t)(row-1024)*256 + k];
    split2(ws, g_bs0[j], g_bs1[j]);
    split2(wp, g_bp0[j], g_bp1[j]);
    if (row < 4) g_bias[j] = bih[j] + bhh[j];
}

// delta = 2 * sum|vt| * eps_tanh  (eps = 2^-10, ~2x the documented MUFU.TANH abs error)
__global__ void vtsum_kernel(const float* __restrict__ vt){
    __shared__ float ws[8];
    int tid = threadIdx.x, lane = tid & 31, wid = tid >> 5;
    float v = fabsf(vt[tid]);
#pragma unroll
    for (int off = 16; off; off >>= 1) v += __shfl_xor_sync(0xffffffffu, v, off);
    if (lane == 0) ws[wid] = v;
    __syncthreads();
    if (tid == 0){
        float s = 0.f;
#pragma unroll
        for (int i = 0; i < 8; i++) s += ws[i];
        g_delta = 2.0f * s * 0.0009765625f;   // 2 * sum|vt| * 2^-10
    }
}

// fused: split enc rows AND compute h0 = c0 = sum_s enc (enc read once)
__global__ void prep_kernel(const float* __restrict__ e0, const float* __restrict__ e1,
                            const float* __restrict__ e2){
    int r = blockIdx.x;                       // 0..9599
    int k = threadIdx.x;
    int t = r / NPT, n = r % NPT;
    const float* e = ((t==0)?e0:((t==1)?e1:e2)) + (size_t)n*(Ssz*256) + k;
    size_t wbase = ((size_t)t*ERT + (size_t)n*Ssz)*256 + k;
    float s = 0.f;
#pragma unroll 1
    for (int ss = 0; ss < Ssz; ss++){
        float v = e[ss*256];
        s += v;
        split2(v, g_es0[wbase + (size_t)ss*256], g_es1[wbase + (size_t)ss*256]);
    }
    g_c[r*256+k] = s;
    split2(s, g_h0s[r*256+k], g_h1s[r*256+k]);
}

// ================= emulated-fp32 GEMM via mma.sync fp16 (2-way split, 3 products) =================
// R12 schedule (proven): CTA tile 128x64, warp tile 32x32, 2-stage, K-chunk 64, 2 CTAs/SM.
#define ASTR   72
#define ATILE  (128*ASTR*2)           // 18432 B
#define BTILE  (64*ASTR*2)            // 9216 B
#define STAGE  (2*ATILE + 2*BTILE)    // 55296 B : A0 A1 B0 B1
#define GSMEM  (2*STAGE)              // 110592 B

__global__ __launch_bounds__(256, 2) void gemm_kernel(
    const __half* __restrict__ A0, const __half* __restrict__ A1,
    const __half* __restrict__ B0, const __half* __restrict__ B1,
    float* __restrict__ Cg, float* __restrict__ Cd)
{
    extern __shared__ __half sh[];
    uint32_t sb = smem_u32(sh);

    const int tid = threadIdx.x, lane = tid & 31, w = tid >> 5;
    const int wm = w & 3, wn = w >> 2;
    const size_t m0 = (size_t)blockIdx.y * 128;
    const int n0 = blockIdx.x * 64;

    float acc0[2][4][4], acc1[2][4][4];
#pragma unroll
    for (int i = 0; i < 2; i++)
#pragma unroll
        for (int j = 0; j < 4; j++)
#pragma unroll
            for (int q = 0; q < 4; q++){ acc0[i][j][q] = 0.f; acc1[i][j][q] = 0.f; }

    const __half* Asrc[2] = { A0 + m0*256, A1 + m0*256 };
    const __half* Bsrc[2] = { B0 + (size_t)n0*256, B1 + (size_t)n0*256 };

    const int arow = wm*32 + (lane & 15);
    const int akof = (lane >> 4) * 8;
    const int brow = wn*32 + (lane & 7) + ((lane >> 4) << 3);
    const int bkof = ((lane >> 3) & 1) * 8;

    auto load_stage = [&](int c){
        uint32_t base = sb + (uint32_t)(c & 1)*STAGE;
#pragma unroll
        for (int t = 0; t < 2; t++){
            const __half* src = Asrc[t] + c*64;
#pragma unroll
            for (int i = 0; i < 4; i++){
                int id = tid + i*256, row = id >> 3, seg = id & 7;
                cpa16(base + t*ATILE + (uint32_t)(row*ASTR + seg*8)*2,
                      src + (size_t)row*256 + seg*8);
            }
        }
#pragma unroll
        for (int t = 0; t < 2; t++){
            const __half* src = Bsrc[t] + c*64;
#pragma unroll
            for (int i = 0; i < 2; i++){
                int id = tid + i*256, row = id >> 3, seg = id & 7;
                cpa16(base + 2*ATILE + t*BTILE + (uint32_t)(row*ASTR + seg*8)*2,
                      src + (size_t)row*256 + seg*8);
            }
        }
        CP_COMMIT();
    };

    load_stage(0);
#pragma unroll 1
    for (int c = 0; c < 4; c++){
        if (c + 1 < 4){ load_stage(c + 1); CP_WAIT1(); }
        else CP_WAIT0();
        __syncthreads();
        uint32_t base = sb + (uint32_t)(c & 1)*STAGE;
        uint32_t a0b = base, a1b = base + ATILE;
        uint32_t b0b = base + 2*ATILE, b1b = b0b + BTILE;
#pragma unroll
        for (int ks = 0; ks < 4; ks++){
            uint32_t b0f[4][2], b1f[4][2];
#pragma unroll
            for (int f2 = 0; f2 < 2; f2++){
                uint32_t off = (uint32_t)((brow + f2*16)*ASTR + ks*16 + bkof)*2;
                uint32_t r[4];
                ldsm4(r, b0b + off);
                b0f[f2*2][0] = r[0]; b0f[f2*2][1] = r[1];
                b0f[f2*2+1][0] = r[2]; b0f[f2*2+1][1] = r[3];
                ldsm4(r, b1b + off);
                b1f[f2*2][0] = r[0]; b1f[f2*2][1] = r[1];
                b1f[f2*2+1][0] = r[2]; b1f[f2*2+1][1] = r[3];
            }
#pragma unroll
            for (int fm = 0; fm < 2; fm++){
                uint32_t aoff = (uint32_t)((arow + fm*16)*ASTR + ks*16 + akof)*2;
                uint32_t a0f[4], a1f[4];
                ldsm4(a0f, a0b + aoff);
                ldsm4(a1f, a1b + aoff);
#pragma unroll
                for (int fn = 0; fn < 4; fn++){
                    mma16816(acc0[fm][fn], a0f, b0f[fn]);
                    mma16816(acc1[fm][fn], a0f, b1f[fn]);
                    mma16816(acc1[fm][fn], a1f, b0f[fn]);
                }
            }
        }
        __syncthreads();
    }

    // epilogue: route n<1024 -> Cg (w=1024), n>=1024 -> Cd (w=256)
    const bool isg = (n0 < 1024);
    float* Cb = isg ? Cg : Cd;
    const int cw = isg ? 1024 : 256;
    const int col = (isg ? n0 : (n0 - 1024)) + wn*32 + 2*(lane & 3);
#pragma unroll
    for (int fm = 0; fm < 2; fm++){
        size_t mrow = m0 + wm*32 + fm*16 + (lane >> 2);
        float* cp0 = Cb + mrow*cw     + col;
        float* cp1 = Cb + (mrow+8)*cw + col;
#pragma unroll
        for (int fn = 0; fn < 4; fn++){
            *(float2*)(cp0 + fn*8) = make_float2(fmaf(acc1[fm][fn][0], RINV, acc0[fm][fn][0]),
                                                 fmaf(acc1[fm][fn][1], RINV, acc0[fm][fn][1]));
            *(float2*)(cp1 + fn*8) = make_float2(fmaf(acc1[fm][fn][2], RINV, acc0[fm][fn][2]),
                                                 fmaf(acc1[fm][fn][3], RINV, acc0[fm][fn][3]));
        }
    }
}

// ================= cell0: initial cell (x=0, no gather) =================
__global__ __launch_bounds__(256) void cell0_kernel(){
    int k = threadIdx.x;
#pragma unroll
    for (int rr = 0; rr < 4; rr++){
        int r = blockIdx.x*4 + rr;
        const float* g = g_graw + (size_t)r*1024;
        float i = fsig (g[k]     + g_bias[k]);
        float f = fsig (g[256+k] + g_bias[256+k]);
        float gv= ftanh(g[512+k] + g_bias[512+k]);
        float o = fsig (g[768+k] + g_bias[768+k]);
        float cn = fmaf(f, g_c[r*256+k], i*gv);
        g_c[r*256+k] = cn;
        split2(o * ftanh(cn), g_h0s[r*256+k], g_h1s[r*256+k]);
    }
}

// approx attention dot (MUFU.TANH, 1 MUFU/term)
__device__ __forceinline__ float attn_dot_a(float4 e0, float4 e1,
                                            const float* dec_s, const float* vt_s, int lane){
    float4 d0 = *(const float4*)(&dec_s[4*lane]);
    float4 d1 = *(const float4*)(&dec_s[128 + 4*lane]);
    float4 v0 = *(const float4*)(&vt_s[4*lane]);
    float4 v1 = *(const float4*)(&vt_s[128 + 4*lane]);
    float p0 = htanh(e0.x + d0.x) * v0.x;
    float p1 = htanh(e0.y + d0.y) * v0.y;
    p0 = fmaf(htanh(e0.z + d0.z), v0.z, p0);
    p1 = fmaf(htanh(e0.w + d0.w), v0.w, p1);
    p0 = fmaf(htanh(e1.x + d1.x), v1.x, p0);
    p1 = fmaf(htanh(e1.y + d1.y), v1.y, p1);
    p0 = fmaf(htanh(e1.z + d1.z), v1.z, p0);
    p1 = fmaf(htanh(e1.w + d1.w), v1.w, p1);
    return p0 + p1;
}
// precise attention dot — EXACT R12 expression & order (certified refine path)
__device__ __forceinline__ float attn_dot_p(float4 e0, float4 e1,
                                            const float* dec_s, const float* vt_s, int lane){
    float4 d0 = *(const float4*)(&dec_s[4*lane]);
    float4 d1 = *(const float4*)(&dec_s[128 + 4*lane]);
    float4 v0 = *(const float4*)(&vt_s[4*lane]);
    float4 v1 = *(const float4*)(&vt_s[128 + 4*lane]);
    float p0 = ftanh(e0.x + d0.x) * v0.x;
    float p1 = ftanh(e0.y + d0.y) * v0.y;
    p0 = fmaf(ftanh(e0.z + d0.z), v0.z, p0);
    p1 = fmaf(ftanh(e0.w + d0.w), v0.w, p1);
    p0 = fmaf(ftanh(e1.x + d1.x), v1.x, p0);
    p1 = fmaf(ftanh(e1.y + d1.y), v1.y, p1);
    p0 = fmaf(ftanh(e1.z + d1.z), v1.z, p0);
    p1 = fmaf(ftanh(e1.w + d1.w), v1.w, p1);
    return p0 + p1;
}
__device__ __forceinline__ float wredu(float p){
#pragma unroll
    for (int off = 16; off; off >>= 1) p += __shfl_xor_sync(0xffffffffu, p, off);
    return p;
}

// ================= fused attention(step) + certified refine + cell(step+1) =================
__global__ __launch_bounds__(256) void attn_cell_kernel(int step, int do_cell,
                                                        const float* __restrict__ vt,
                                                        float* __restrict__ out){
    __shared__ float dec_s[256], vt_s[256], u_s[Ssz];
    __shared__ float maxA_sh;
    __shared__ int cnt_sh, cand_sh[Ssz], idx_sh;
    int tid = threadIdx.x, wid = tid >> 5, lane = tid & 31;
    int r = blockIdx.x;                       // global row 0..9599
    int t = r / NPT, n = r % NPT;
    dec_s[tid] = g_dec[(size_t)r*256 + tid];
    vt_s[tid]  = vt[tid];
    if (tid == 0) cnt_sh = 0;
    __syncthreads();

    const float* eb = et_ptr(t) + (size_t)n*Ssz*256;   // fully contiguous 51.2 KB
    // approx pass: s = wid + {0,8,16,24,32,40} in pairs, then 48+wid for wid<2
#pragma unroll 1
    for (int s = wid; s + 8 < Ssz; s += 16){
        const float4* epA = (const float4*)(eb + (size_t)s*256);
        const float4* epB = (const float4*)(eb + (size_t)(s+8)*256);
        float4 a0 = epA[lane], a1 = epA[32 + lane];
        float4 b0 = epB[lane], b1 = epB[32 + lane];
        float pA = wredu(attn_dot_a(a0, a1, dec_s, vt_s, lane));
        float pB = wredu(attn_dot_a(b0, b1, dec_s, vt_s, lane));
        if (lane == 0){ u_s[s] = pA; u_s[s + 8] = pB; }
    }
    if (wid < 2){
        int s = 48 + wid;
        const float4* ep = (const float4*)(eb + (size_t)s*256);
        float4 e0 = ep[lane], e1 = ep[32 + lane];
        float p = wredu(attn_dot_a(e0, e1, dec_s, vt_s, lane));
        if (lane == 0) u_s[s] = p;
    }
    __syncthreads();

    // approx max (warp 0)
    if (wid == 0){
        float ua = u_s[lane];
        float ub = (lane + 32 < Ssz) ? u_s[lane + 32] : -CUDART_INF_F;
        float bm = fmaxf(ua, ub);
#pragma unroll
        for (int off = 16; off; off >>= 1)
            bm = fmaxf(bm, __shfl_xor_sync(0xffffffffu, bm, off));
        if (lane == 0) maxA_sh = bm;
    }
    __syncthreads();

    // candidate set: everything within the certified margin of the approx max
    if (tid < Ssz && u_s[tid] >= maxA_sh - g_delta){
        int slot = atomicAdd(&cnt_sh, 1);
        cand_sh[slot] = tid;
    }
    __syncthreads();

    // precise recompute of candidates (exact R12 path -> exact argmax trajectory)
    int cnt = cnt_sh;
#pragma unroll 1
    for (int ci = wid; ci < cnt; ci += 8){
        int s = cand_sh[ci];
        const float4* ep = (const float4*)(eb + (size_t)s*256);
        float4 e0 = ep[lane], e1 = ep[32 + lane];
        float p = wredu(attn_dot_p(e0, e1, dec_s, vt_s, lane));
        if (lane == 0) u_s[s] = p;
    }
    __syncthreads();

    // final argmax + softmax (R12 code on refined u_s)
    if (wid == 0){
        float ua = u_s[lane];
        float ub = (lane + 32 < Ssz) ? u_s[lane + 32] : -CUDART_INF_F;
        float bm = ua; int bi = lane;
        if (ub > bm){ bm = ub; bi = lane + 32; }
#pragma unroll
        for (int off = 16; off; off >>= 1){
            float vm = __shfl_xor_sync(0xffffffffu, bm, off);
            int   vi = __shfl_xor_sync(0xffffffffu, bi, off);
            if (vm > bm || (vm == bm && vi < bi)){ bm = vm; bi = vi; }
        }
        float ea = __expf(ua - bm);
        float eb2 = (lane + 32 < Ssz) ? __expf(ub - bm) : 0.f;
        float sm = ea + eb2;
#pragma unroll
        for (int off = 16; off; off >>= 1) sm += __shfl_xor_sync(0xffffffffu, sm, off);
        float inv = 1.0f / sm;
        float* so = out + (size_t)t*8160000 + (size_t)n*2500 + step*50;
        so[lane] = ea * inv;
        if (lane + 32 < Ssz) so[lane + 32] = eb2 * inv;
        if (lane == 0){
            idx_sh = bi;
            out[(size_t)t*8160000 + 8000000 + (size_t)n*50 + step] = (float)bi;
        }
    }
    __syncthreads();

    if (do_cell){
        int k = tid;
        const float* g = g_graw + (size_t)r*1024;
        const float* ex = gx_ptr(t) + (size_t)(n*Ssz + idx_sh)*1024;
        float i = fsig (g[k]     + ex[k]     + g_bias[k]);
        float f = fsig (g[256+k] + ex[256+k] + g_bias[256+k]);
        float gv= ftanh(g[512+k] + ex[512+k] + g_bias[512+k]);
        float o = fsig (g[768+k] + ex[768+k] + g_bias[768+k]);
        float cn = fmaf(f, g_c[r*256+k], i*gv);
        g_c[r*256+k] = cn;
        split2(o * ftanh(cn), g_h0s[r*256+k], g_h1s[r*256+k]);
    }
}

// ================= launch =================
extern "C" void kernel_launch(void* const* d_in, const int* in_sizes, int n_in,
                              void* d_out, int out_size){
    const float* home = (const float*)d_in[0];
    const float* vis  = (const float*)d_in[1];
    const float* team = (const float*)d_in[2];
    const float* Wih  = (const float*)d_in[3];
    const float* Whh  = (const float*)d_in[4];
    const float* bih  = (const float*)d_in[5];
    const float* bhh  = (const float*)d_in[6];
    const float* W1   = (const float*)d_in[7];
    const float* W2   = (const float*)d_in[8];
    const float* vt   = (const float*)d_in[9];
    float* out = (float*)d_out;

    cudaFuncSetAttribute(gemm_kernel, cudaFuncAttributeMaxDynamicSharedMemorySize, GSMEM);

    pack_b_kernel<<<NB, 256>>>(Whh, W2, Wih, W1, bih, bhh);
    vtsum_kernel<<<1, 256>>>(vt);
    prep_kernel<<<NROW, 256>>>(home, vis, team);

    __half *es0, *es1, *bp0, *bp1, *bs0, *bs1, *h0, *h1;
    float *gx0, *gx1, *gx2, *et0, *et1, *et2, *graw, *dec;
    cudaGetSymbolAddress((void**)&es0, g_es0);  cudaGetSymbolAddress((void**)&es1, g_es1);
    cudaGetSymbolAddress((void**)&bp0, g_bp0);  cudaGetSymbolAddress((void**)&bp1, g_bp1);
    cudaGetSymbolAddress((void**)&bs0, g_bs0);  cudaGetSymbolAddress((void**)&bs1, g_bs1);
    cudaGetSymbolAddress((void**)&h0,  g_h0s);  cudaGetSymbolAddress((void**)&h1,  g_h1s);
    cudaGetSymbolAddress((void**)&gx0, g_gx0);  cudaGetSymbolAddress((void**)&gx1, g_gx1);
    cudaGetSymbolAddress((void**)&gx2, g_gx2);
    cudaGetSymbolAddress((void**)&et0, g_et0);  cudaGetSymbolAddress((void**)&et1, g_et1);
    cudaGetSymbolAddress((void**)&et2, g_et2);
    cudaGetSymbolAddress((void**)&graw, g_graw); cudaGetSymbolAddress((void**)&dec, g_dec);

    float* gxs[3] = {gx0, gx1, gx2};
    float* ets[3] = {et0, et1, et2};
    for (int t = 0; t < 3; t++){
        size_t off = (size_t)t * ERT * 256;
        gemm_kernel<<<dim3(20, 1250), 256, GSMEM>>>(es0 + off, es1 + off, bp0, bp1,
                                                    gxs[t], ets[t]);
    }

    // bootstrap: gates from h0 -> cell0 -> gates+dec
    gemm_kernel<<<dim3(20, 75), 256, GSMEM>>>(h0, h1, bs0, bs1, graw, dec);
    cell0_kernel<<<NROW/4, 256>>>();
    gemm_kernel<<<dim3(20, 75), 256, GSMEM>>>(h0, h1, bs0, bs1, graw, dec);

    for (int i = 0; i < Ssz; i++){
        attn_cell_kernel<<<NROW, 256>>>(i, (i + 1 < Ssz) ? 1 : 0, vt, out);
        if (i + 1 < Ssz)
            gemm_kernel<<<dim3(20, 75), 256, GSMEM>>>(h0, h1, bs0, bs1, graw, dec);
    }
}

// round 16
// speedup vs baseline: 1.2049x; 1.1141x over previous
#include <cuda_runtime.h>
#include <cuda_fp16.h>
#include <math_constants.h>
#include <cstdint>

#define Ssz  50
#define NPT  3200
#define NROW 9600
#define ERT  160000
#define NB   1280

#define RSCALE   2048.0f          // residual scale 2^11
#define RINV     (1.0f/2048.0f)

// ================= static device scratch (no allocation) =================
static __device__ __half g_es0[(size_t)480000*256], g_es1[(size_t)480000*256];
static __device__ float g_gx0[(size_t)ERT*1024], g_gx1[(size_t)ERT*1024], g_gx2[(size_t)ERT*1024];
static __device__ float g_et0[(size_t)ERT*256],  g_et1[(size_t)ERT*256],  g_et2[(size_t)ERT*256];
static __device__ __half g_eth0[(size_t)ERT*256], g_eth1[(size_t)ERT*256], g_eth2[(size_t)ERT*256];
static __device__ __half g_h0s[NROW*256], g_h1s[NROW*256];
static __device__ float g_c[NROW*256];
static __device__ float g_graw[(size_t)NROW*1024];
static __device__ float g_dec[(size_t)NROW*256];
static __device__ __half g_bs0[NB*256], g_bs1[NB*256];   // [Whh;W2] splits
static __device__ __half g_bp0[NB*256], g_bp1[NB*256];   // [Wih;W1] splits
static __device__ float g_bias[1024];
static __device__ float g_delta;                          // certified argmax margin
static __device__ int   g_absmax;                         // max|et| as ordered-int (monotone)

__device__ __forceinline__ float* gx_ptr(int t){ return (t==0)?g_gx0:((t==1)?g_gx1:g_gx2); }
__device__ __forceinline__ float* et_ptr(int t){ return (t==0)?g_et0:((t==1)?g_et1:g_et2); }
__device__ __forceinline__ __half* eth_ptr(int t){ return (t==0)?g_eth0:((t==1)?g_eth1:g_eth2); }
__device__ __forceinline__ void split2(float v, __half& a, __half& b){
    a = __float2half_rn(v);
    float r = v - __half2float(a);
    b = __float2half_rn(r * RSCALE);
}
__device__ __forceinline__ float fsig(float x){ return __fdividef(1.f, 1.f + __expf(-x)); }
__device__ __forceinline__ float ftanh(float x){ return 1.f - __fdividef(2.f, 1.f + __expf(2.f*x)); }
__device__ __forceinline__ float htanh(float x){
    float y;
    asm("tanh.approx.f32 %0, %1;" : "=f"(y) : "f"(x));
    return y;
}

// ================= baseline-PTX tensor helpers =================
__device__ __forceinline__ uint32_t smem_u32(const void* p){
    uint32_t a;
    asm("{ .reg .u64 t; cvta.to.shared.u64 t, %1; cvt.u32.u64 %0, t; }" : "=r"(a) : "l"(p));
    return a;
}
__device__ __forceinline__ void ldsm4(uint32_t* r, uint32_t addr){
    asm volatile("ldmatrix.sync.aligned.m8n8.x4.shared.b16 {%0,%1,%2,%3}, [%4];"
        : "=r"(r[0]), "=r"(r[1]), "=r"(r[2]), "=r"(r[3]) : "r"(addr));
}
__device__ __forceinline__ void mma16816(float* c, const uint32_t* a, const uint32_t* b){
    asm volatile("mma.sync.aligned.m16n8k16.row.col.f32.f16.f16.f32 "
        "{%0,%1,%2,%3}, {%4,%5,%6,%7}, {%8,%9}, {%0,%1,%2,%3};"
        : "+f"(c[0]), "+f"(c[1]), "+f"(c[2]), "+f"(c[3])
        : "r"(a[0]), "r"(a[1]), "r"(a[2]), "r"(a[3]), "r"(b[0]), "r"(b[1]));
}
__device__ __forceinline__ void cpa16(uint32_t d, const void* s){
    asm volatile("cp.async.cg.shared.global [%0], [%1], 16;" :: "r"(d), "l"(s));
}
#define CP_COMMIT() asm volatile("cp.async.commit_group;" ::: "memory")
#define CP_WAIT0()  asm volatile("cp.async.wait_group 0;" ::: "memory")
#define CP_WAIT1()  asm volatile("cp.async.wait_group 1;" ::: "memory")

// ================= prep kernels =================
__global__ void pack_b_kernel(const float* __restrict__ Whh, const float* __restrict__ W2,
                              const float* __restrict__ Wih, const float* __restrict__ W1,
                              const float* __restrict__ bih, const float* __restrict__ bhh){
    int row = blockIdx.x, k = threadIdx.x, j = row*256 + k;
    float ws = (row < 1024) ? Whh[j] : W2[(size_t)(row-1024)*256 + k];
    float wp = (row < 1024) ? Wih[j] : W1[(size_t)(row-1024)*256 + k];
    split2(ws, g_bs0[j], g_bs1[j]);
    split2(wp, g_bp0[j], g_bp1[j]);
    if (row < 4) g_bias[j] = bih[j] + bhh[j];
}

// delta = 2.5 * sum|vt| * (absmax*2^-11 + 2^-10)  — certified 2x + 1.25 safety
__global__ void vtsum_kernel(const float* __restrict__ vt){
    __shared__ float ws[8];
    int tid = threadIdx.x, lane = tid & 31, wid = tid >> 5;
    float v = fabsf(vt[tid]);
#pragma unroll
    for (int off = 16; off; off >>= 1) v += __shfl_xor_sync(0xffffffffu, v, off);
    if (lane == 0) ws[wid] = v;
    __syncthreads();
    if (tid == 0){
        float s = 0.f;
#pragma unroll
        for (int i = 0; i < 8; i++) s += ws[i];
        float am = __int_as_float(g_absmax);
        g_delta = 2.5f * s * (am * 4.8828125e-4f + 9.765625e-4f);
    }
}

// fused: split enc rows AND compute h0 = c0 = sum_s enc (enc read once)
__global__ void prep_kernel(const float* __restrict__ e0, const float* __restrict__ e1,
                            const float* __restrict__ e2){
    int r = blockIdx.x;                       // 0..9599
    int k = threadIdx.x;
    int t = r / NPT, n = r % NPT;
    const float* e = ((t==0)?e0:((t==1)?e1:e2)) + (size_t)n*(Ssz*256) + k;
    size_t wbase = ((size_t)t*ERT + (size_t)n*Ssz)*256 + k;
    float s = 0.f;
#pragma unroll 1
    for (int ss = 0; ss < Ssz; ss++){
        float v = e[ss*256];
        s += v;
        split2(v, g_es0[wbase + (size_t)ss*256], g_es1[wbase + (size_t)ss*256]);
    }
    g_c[r*256+k] = s;
    split2(s, g_h0s[r*256+k], g_h1s[r*256+k]);
}

// ================= emulated-fp32 GEMM via mma.sync fp16 (2-way split, 3 products) =================
// R12 schedule (proven): CTA tile 128x64, warp tile 32x32, 2-stage, K-chunk 64, 2 CTAs/SM.
// Epilogue: n<1024 -> Cg (w=1024); n>=1024 -> Cd (w=256) and, if Ch, fp16 copy + absmax.
#define ASTR   72
#define ATILE  (128*ASTR*2)           // 18432 B
#define BTILE  (64*ASTR*2)            // 9216 B
#define STAGE  (2*ATILE + 2*BTILE)    // 55296 B : A0 A1 B0 B1
#define GSMEM  (2*STAGE)              // 110592 B

__global__ __launch_bounds__(256, 2) void gemm_kernel(
    const __half* __restrict__ A0, const __half* __restrict__ A1,
    const __half* __restrict__ B0, const __half* __restrict__ B1,
    float* __restrict__ Cg, float* __restrict__ Cd, __half* __restrict__ Ch)
{
    extern __shared__ __half sh[];
    uint32_t sb = smem_u32(sh);

    const int tid = threadIdx.x, lane = tid & 31, w = tid >> 5;
    const int wm = w & 3, wn = w >> 2;
    const size_t m0 = (size_t)blockIdx.y * 128;
    const int n0 = blockIdx.x * 64;

    float acc0[2][4][4], acc1[2][4][4];
#pragma unroll
    for (int i = 0; i < 2; i++)
#pragma unroll
        for (int j = 0; j < 4; j++)
#pragma unroll
            for (int q = 0; q < 4; q++){ acc0[i][j][q] = 0.f; acc1[i][j][q] = 0.f; }

    const __half* Asrc[2] = { A0 + m0*256, A1 + m0*256 };
    const __half* Bsrc[2] = { B0 + (size_t)n0*256, B1 + (size_t)n0*256 };

    const int arow = wm*32 + (lane & 15);
    const int akof = (lane >> 4) * 8;
    const int brow = wn*32 + (lane & 7) + ((lane >> 4) << 3);
    const int bkof = ((lane >> 3) & 1) * 8;

    auto load_stage = [&](int c){
        uint32_t base = sb + (uint32_t)(c & 1)*STAGE;
#pragma unroll
        for (int t = 0; t < 2; t++){
            const __half* src = Asrc[t] + c*64;
#pragma unroll
            for (int i = 0; i < 4; i++){
                int id = tid + i*256, row = id >> 3, seg = id & 7;
                cpa16(base + t*ATILE + (uint32_t)(row*ASTR + seg*8)*2,
                      src + (size_t)row*256 + seg*8);
            }
        }
#pragma unroll
        for (int t = 0; t < 2; t++){
            const __half* src = Bsrc[t] + c*64;
#pragma unroll
            for (int i = 0; i < 2; i++){
                int id = tid + i*256, row = id >> 3, seg = id & 7;
                cpa16(base + 2*ATILE + t*BTILE + (uint32_t)(row*ASTR + seg*8)*2,
                      src + (size_t)row*256 + seg*8);
            }
        }
        CP_COMMIT();
    };

    load_stage(0);
#pragma unroll 1
    for (int c = 0; c < 4; c++){
        if (c + 1 < 4){ load_stage(c + 1); CP_WAIT1(); }
        else CP_WAIT0();
        __syncthreads();
        uint32_t base = sb + (uint32_t)(c & 1)*STAGE;
        uint32_t a0b = base, a1b = base + ATILE;
        uint32_t b0b = base + 2*ATILE, b1b = b0b + BTILE;
#pragma unroll
        for (int ks = 0; ks < 4; ks++){
            uint32_t b0f[4][2], b1f[4][2];
#pragma unroll
            for (int f2 = 0; f2 < 2; f2++){
                uint32_t off = (uint32_t)((brow + f2*16)*ASTR + ks*16 + bkof)*2;
                uint32_t r[4];
                ldsm4(r, b0b + off);
                b0f[f2*2][0] = r[0]; b0f[f2*2][1] = r[1];
                b0f[f2*2+1][0] = r[2]; b0f[f2*2+1][1] = r[3];
                ldsm4(r, b1b + off);
                b1f[f2*2][0] = r[0]; b1f[f2*2][1] = r[1];
                b1f[f2*2+1][0] = r[2]; b1f[f2*2+1][1] = r[3];
            }
#pragma unroll
            for (int fm = 0; fm < 2; fm++){
                uint32_t aoff = (uint32_t)((arow + fm*16)*ASTR + ks*16 + akof)*2;
                uint32_t a0f[4], a1f[4];
                ldsm4(a0f, a0b + aoff);
                ldsm4(a1f, a1b + aoff);
#pragma unroll
                for (int fn = 0; fn < 4; fn++){
                    mma16816(acc0[fm][fn], a0f, b0f[fn]);
                    mma16816(acc1[fm][fn], a0f, b1f[fn]);
                    mma16816(acc1[fm][fn], a1f, b0f[fn]);
                }
            }
        }
        __syncthreads();
    }

    // epilogue
    const bool isg = (n0 < 1024);
    float* Cb = isg ? Cg : Cd;
    const int cw = isg ? 1024 : 256;
    const int col = (isg ? n0 : (n0 - 1024)) + wn*32 + 2*(lane & 3);
    float am = 0.f;
#pragma unroll
    for (int fm = 0; fm < 2; fm++){
        size_t mrow = m0 + wm*32 + fm*16 + (lane >> 2);
#pragma unroll
        for (int fn = 0; fn < 4; fn++){
            float2 r0 = make_float2(fmaf(acc1[fm][fn][0], RINV, acc0[fm][fn][0]),
                                    fmaf(acc1[fm][fn][1], RINV, acc0[fm][fn][1]));
            float2 r1 = make_float2(fmaf(acc1[fm][fn][2], RINV, acc0[fm][fn][2]),
                                    fmaf(acc1[fm][fn][3], RINV, acc0[fm][fn][3]));
            *(float2*)(Cb + mrow*cw     + col + fn*8) = r0;
            *(float2*)(Cb + (mrow+8)*cw + col + fn*8) = r1;
            if (!isg && Ch){
                *(__half2*)(Ch + mrow*256     + col + fn*8) = __floats2half2_rn(r0.x, r0.y);
                *(__half2*)(Ch + (mrow+8)*256 + col + fn*8) = __floats2half2_rn(r1.x, r1.y);
                am = fmaxf(am, fmaxf(fmaxf(fabsf(r0.x), fabsf(r0.y)),
                                     fmaxf(fabsf(r1.x), fabsf(r1.y))));
            }
        }
    }
    if (!isg && Ch){
#pragma unroll
        for (int off = 16; off; off >>= 1)
            am = fmaxf(am, __shfl_xor_sync(0xffffffffu, am, off));
        if (lane == 0) atomicMax(&g_absmax, __float_as_int(am));
    }
}

// ================= cell0: initial cell (x=0, no gather) =================
__global__ __launch_bounds__(256) void cell0_kernel(){
    int k = threadIdx.x;
#pragma unroll
    for (int rr = 0; rr < 4; rr++){
        int r = blockIdx.x*4 + rr;
        const float* g = g_graw + (size_t)r*1024;
        float i = fsig (g[k]     + g_bias[k]);
        float f = fsig (g[256+k] + g_bias[256+k]);
        float gv= ftanh(g[512+k] + g_bias[512+k]);
        float o = fsig (g[768+k] + g_bias[768+k]);
        float cn = fmaf(f, g_c[r*256+k], i*gv);
        g_c[r*256+k] = cn;
        split2(o * ftanh(cn), g_h0s[r*256+k], g_h1s[r*256+k]);
    }
}

// approx attention dot on fp16 et row: one 16B load/lane (k = 8*lane..8*lane+7)
__device__ __forceinline__ float attn_dot_h(uint4 raw, const float* dec_s,
                                            const float* vt_s, int lane){
    __half2* hp = (__half2*)&raw;
    float2 e01 = __half22float2(hp[0]);
    float2 e23 = __half22float2(hp[1]);
    float2 e45 = __half22float2(hp[2]);
    float2 e67 = __half22float2(hp[3]);
    float4 d0 = *(const float4*)(&dec_s[8*lane]);
    float4 d1 = *(const float4*)(&dec_s[8*lane + 4]);
    float4 v0 = *(const float4*)(&vt_s[8*lane]);
    float4 v1 = *(const float4*)(&vt_s[8*lane + 4]);
    float p0 = htanh(e01.x + d0.x) * v0.x;
    float p1 = htanh(e01.y + d0.y) * v0.y;
    p0 = fmaf(htanh(e23.x + d0.z), v0.z, p0);
    p1 = fmaf(htanh(e23.y + d0.w), v0.w, p1);
    p0 = fmaf(htanh(e45.x + d1.x), v1.x, p0);
    p1 = fmaf(htanh(e45.y + d1.y), v1.y, p1);
    p0 = fmaf(htanh(e67.x + d1.z), v1.z, p0);
    p1 = fmaf(htanh(e67.y + d1.w), v1.w, p1);
    return p0 + p1;
}
// precise attention dot — EXACT R12 expression & order (certified refine path)
__device__ __forceinline__ float attn_dot_p(float4 e0, float4 e1,
                                            const float* dec_s, const float* vt_s, int lane){
    float4 d0 = *(const float4*)(&dec_s[4*lane]);
    float4 d1 = *(const float4*)(&dec_s[128 + 4*lane]);
    float4 v0 = *(const float4*)(&vt_s[4*lane]);
    float4 v1 = *(const float4*)(&vt_s[128 + 4*lane]);
    float p0 = ftanh(e0.x + d0.x) * v0.x;
    float p1 = ftanh(e0.y + d0.y) * v0.y;
    p0 = fmaf(ftanh(e0.z + d0.z), v0.z, p0);
    p1 = fmaf(ftanh(e0.w + d0.w), v0.w, p1);
    p0 = fmaf(ftanh(e1.x + d1.x), v1.x, p0);
    p1 = fmaf(ftanh(e1.y + d1.y), v1.y, p1);
    p0 = fmaf(ftanh(e1.z + d1.z), v1.z, p0);
    p1 = fmaf(ftanh(e1.w + d1.w), v1.w, p1);
    return p0 + p1;
}
__device__ __forceinline__ float wredu(float p){
#pragma unroll
    for (int off = 16; off; off >>= 1) p += __shfl_xor_sync(0xffffffffu, p, off);
    return p;
}

// ================= fused attention(step, fp16 stream) + certified refine + cell(step+1) =================
__global__ __launch_bounds__(256) void attn_cell_kernel(int step, int do_cell,
                                                        const float* __restrict__ vt,
                                                        float* __restrict__ out){
    __shared__ float dec_s[256], vt_s[256], u_s[Ssz];
    __shared__ float maxA_sh;
    __shared__ int cnt_sh, cand_sh[Ssz], idx_sh;
    int tid = threadIdx.x, wid = tid >> 5, lane = tid & 31;
    int r = blockIdx.x;                       // global row 0..9599
    int t = r / NPT, n = r % NPT;
    dec_s[tid] = g_dec[(size_t)r*256 + tid];
    vt_s[tid]  = vt[tid];
    if (tid == 0) cnt_sh = 0;
    __syncthreads();

    const char* ebh = (const char*)(eth_ptr(t) + (size_t)n*Ssz*256);  // 512 B per s-row
    // approx pass on fp16 et: s = wid + {0,8,16,24,32,40} pairs, then 48+wid for wid<2
#pragma unroll 1
    for (int s = wid; s + 8 < Ssz; s += 16){
        uint4 rA = *(const uint4*)(ebh + (size_t)s*512 + lane*16);
        uint4 rB = *(const uint4*)(ebh + (size_t)(s+8)*512 + lane*16);
        float pA = wredu(attn_dot_h(rA, dec_s, vt_s, lane));
        float pB = wredu(attn_dot_h(rB, dec_s, vt_s, lane));
        if (lane == 0){ u_s[s] = pA; u_s[s + 8] = pB; }
    }
    if (wid < 2){
        int s = 48 + wid;
        uint4 rA = *(const uint4*)(ebh + (size_t)s*512 + lane*16);
        float p = wredu(attn_dot_h(rA, dec_s, vt_s, lane));
        if (lane == 0) u_s[s] = p;
    }
    __syncthreads();

    // approx max (warp 0)
    if (wid == 0){
        float ua = u_s[lane];
        float ub = (lane + 32 < Ssz) ? u_s[lane + 32] : -CUDART_INF_F;
        float bm = fmaxf(ua, ub);
#pragma unroll
        for (int off = 16; off; off >>= 1)
            bm = fmaxf(bm, __shfl_xor_sync(0xffffffffu, bm, off));
        if (lane == 0) maxA_sh = bm;
    }
    __syncthreads();

    // candidate set: everything within the certified margin of the approx max
    if (tid < Ssz && u_s[tid] >= maxA_sh - g_delta){
        int slot = atomicAdd(&cnt_sh, 1);
        cand_sh[slot] = tid;
    }
    __syncthreads();

    // precise recompute of candidates from fp32 et (exact R12 path -> exact argmax)
    const float* eb = et_ptr(t) + (size_t)n*Ssz*256;
    int cnt = cnt_sh;
#pragma unroll 1
    for (int ci = wid; ci < cnt; ci += 8){
        int s = cand_sh[ci];
        const float4* ep = (const float4*)(eb + (size_t)s*256);
        float4 e0 = ep[lane], e1 = ep[32 + lane];
        float p = wredu(attn_dot_p(e0, e1, dec_s, vt_s, lane));
        if (lane == 0) u_s[s] = p;
    }
    __syncthreads();

    // final argmax + softmax (R12 code on refined u_s)
    if (wid == 0){
        float ua = u_s[lane];
        float ub = (lane + 32 < Ssz) ? u_s[lane + 32] : -CUDART_INF_F;
        float bm = ua; int bi = lane;
        if (ub > bm){ bm = ub; bi = lane + 32; }
#pragma unroll
        for (int off = 16; off; off >>= 1){
            float vm = __shfl_xor_sync(0xffffffffu, bm, off);
            int   vi = __shfl_xor_sync(0xffffffffu, bi, off);
            if (vm > bm || (vm == bm && vi < bi)){ bm = vm; bi = vi; }
        }
        float ea = __expf(ua - bm);
        float eb2 = (lane + 32 < Ssz) ? __expf(ub - bm) : 0.f;
        float sm = ea + eb2;
#pragma unroll
        for (int off = 16; off; off >>= 1) sm += __shfl_xor_sync(0xffffffffu, sm, off);
        float inv = 1.0f / sm;
        float* so = out + (size_t)t*8160000 + (size_t)n*2500 + step*50;
        so[lane] = ea * inv;
        if (lane + 32 < Ssz) so[lane + 32] = eb2 * inv;
        if (lane == 0){
            idx_sh = bi;
            out[(size_t)t*8160000 + 8000000 + (size_t)n*50 + step] = (float)bi;
        }
    }
    __syncthreads();

    if (do_cell){
        int k = tid;
        const float* g = g_graw + (size_t)r*1024;
        const float* ex = gx_ptr(t) + (size_t)(n*Ssz + idx_sh)*1024;
        float i = fsig (g[k]     + ex[k]     + g_bias[k]);
        float f = fsig (g[256+k] + ex[256+k] + g_bias[256+k]);
        float gv= ftanh(g[512+k] + ex[512+k] + g_bias[512+k]);
        float o = fsig (g[768+k] + ex[768+k] + g_bias[768+k]);
        float cn = fmaf(f, g_c[r*256+k], i*gv);
        g_c[r*256+k] = cn;
        split2(o * ftanh(cn), g_h0s[r*256+k], g_h1s[r*256+k]);
    }
}

// ================= launch =================
extern "C" void kernel_launch(void* const* d_in, const int* in_sizes, int n_in,
                              void* d_out, int out_size){
    const float* home = (const float*)d_in[0];
    const float* vis  = (const float*)d_in[1];
    const float* team = (const float*)d_in[2];
    const float* Wih  = (const float*)d_in[3];
    const float* Whh  = (const float*)d_in[4];
    const float* bih  = (const float*)d_in[5];
    const float* bhh  = (const float*)d_in[6];
    const float* W1   = (const float*)d_in[7];
    const float* W2   = (const float*)d_in[8];
    const float* vt   = (const float*)d_in[9];
    float* out = (float*)d_out;

    cudaFuncSetAttribute(gemm_kernel, cudaFuncAttributeMaxDynamicSharedMemorySize, GSMEM);

    pack_b_kernel<<<NB, 256>>>(Whh, W2, Wih, W1, bih, bhh);
    prep_kernel<<<NROW, 256>>>(home, vis, team);

    __half *es0, *es1, *bp0, *bp1, *bs0, *bs1, *h0, *h1, *eth0, *eth1, *eth2;
    float *gx0, *gx1, *gx2, *et0, *et1, *et2, *graw, *dec;
    cudaGetSymbolAddress((void**)&es0, g_es0);  cudaGetSymbolAddress((void**)&es1, g_es1);
    cudaGetSymbolAddress((void**)&bp0, g_bp0);  cudaGetSymbolAddress((void**)&bp1, g_bp1);
    cudaGetSymbolAddress((void**)&bs0, g_bs0);  cudaGetSymbolAddress((void**)&bs1, g_bs1);
    cudaGetSymbolAddress((void**)&h0,  g_h0s);  cudaGetSymbolAddress((void**)&h1,  g_h1s);
    cudaGetSymbolAddress((void**)&gx0, g_gx0);  cudaGetSymbolAddress((void**)&gx1, g_gx1);
    cudaGetSymbolAddress((void**)&gx2, g_gx2);
    cudaGetSymbolAddress((void**)&et0, g_et0);  cudaGetSymbolAddress((void**)&et1, g_et1);
    cudaGetSymbolAddress((void**)&et2, g_et2);
    cudaGetSymbolAddress((void**)&eth0, g_eth0); cudaGetSymbolAddress((void**)&eth1, g_eth1);
    cudaGetSymbolAddress((void**)&eth2, g_eth2);
    cudaGetSymbolAddress((void**)&graw, g_graw); cudaGetSymbolAddress((void**)&dec, g_dec);

    float* gxs[3] = {gx0, gx1, gx2};
    float* ets[3] = {et0, et1, et2};
    __half* eths[3] = {eth0, eth1, eth2};
    for (int t = 0; t < 3; t++){
        size_t off = (size_t)t * ERT * 256;
        gemm_kernel<<<dim3(20, 1250), 256, GSMEM>>>(es0 + off, es1 + off, bp0, bp1,
                                                    gxs[t], ets[t], eths[t]);
    }
    vtsum_kernel<<<1, 256>>>(vt);     // after et gemms: needs g_absmax

    // bootstrap: gates from h0 -> cell0 -> gates+dec
    gemm_kernel<<<dim3(20, 75), 256, GSMEM>>>(h0, h1, bs0, bs1, graw, dec, (__half*)0);
    cell0_kernel<<<NROW/4, 256>>>();
    gemm_kernel<<<dim3(20, 75), 256, GSMEM>>>(h0, h1, bs0, bs1, graw, dec, (__half*)0);

    for (int i = 0; i < Ssz; i++){
        attn_cell_kernel<<<NROW, 256>>>(i, (i + 1 < Ssz) ? 1 : 0, vt, out);
        if (i + 1 < Ssz)
            gemm_kernel<<<dim3(20, 75), 256, GSMEM>>>(h0, h1, bs0, bs1, graw, dec, (__half*)0);
    }
}

// round 17
// speedup vs baseline: 1.2559x; 1.0424x over previous
#include <cuda_runtime.h>
#include <cuda_fp16.h>
#include <math_constants.h>
#include <cstdint>

#define Ssz  50
#define NPT  3200
#define NROW 9600
#define ERT  160000
#define NB   1280

#define RSCALE   2048.0f          // residual scale 2^11
#define RINV     (1.0f/2048.0f)

// ================= static device scratch (no allocation) =================
static __device__ __half g_es0[(size_t)480000*256], g_es1[(size_t)480000*256];
static __device__ float g_gx0[(size_t)ERT*1024], g_gx1[(size_t)ERT*1024], g_gx2[(size_t)ERT*1024];
static __device__ float g_et0[(size_t)ERT*256],  g_et1[(size_t)ERT*256],  g_et2[(size_t)ERT*256];
static __device__ __half g_eth0[(size_t)ERT*256], g_eth1[(size_t)ERT*256], g_eth2[(size_t)ERT*256];
static __device__ __half g_h0s[NROW*256], g_h1s[NROW*256];
static __device__ float g_c[NROW*256];
static __device__ float g_graw[(size_t)NROW*1024];
static __device__ float g_dec[(size_t)NROW*256];
static __device__ __half g_bs0[NB*256], g_bs1[NB*256];   // [Whh;W2] splits
static __device__ __half g_bp0[NB*256], g_bp1[NB*256];   // [Wih;W1] splits
static __device__ float g_bias[1024];
static __device__ float g_delta;                          // certified argmax margin
static __device__ int   g_absmax;                         // max|et| as ordered-int (monotone)

__device__ __forceinline__ float* gx_ptr(int t){ return (t==0)?g_gx0:((t==1)?g_gx1:g_gx2); }
__device__ __forceinline__ float* et_ptr(int t){ return (t==0)?g_et0:((t==1)?g_et1:g_et2); }
__device__ __forceinline__ __half* eth_ptr(int t){ return (t==0)?g_eth0:((t==1)?g_eth1:g_eth2); }
__device__ __forceinline__ void split2(float v, __half& a, __half& b){
    a = __float2half_rn(v);
    float r = v - __half2float(a);
    b = __float2half_rn(r * RSCALE);
}
__device__ __forceinline__ float fsig(float x){ return __fdividef(1.f, 1.f + __expf(-x)); }
__device__ __forceinline__ float ftanh(float x){ return 1.f - __fdividef(2.f, 1.f + __expf(2.f*x)); }
__device__ __forceinline__ float htanh(float x){
    float y;
    asm("tanh.approx.f32 %0, %1;" : "=f"(y) : "f"(x));
    return y;
}

// ================= baseline-PTX tensor helpers =================
__device__ __forceinline__ uint32_t smem_u32(const void* p){
    uint32_t a;
    asm("{ .reg .u64 t; cvta.to.shared.u64 t, %1; cvt.u32.u64 %0, t; }" : "=r"(a) : "l"(p));
    return a;
}
__device__ __forceinline__ void ldsm4(uint32_t* r, uint32_t addr){
    asm volatile("ldmatrix.sync.aligned.m8n8.x4.shared.b16 {%0,%1,%2,%3}, [%4];"
        : "=r"(r[0]), "=r"(r[1]), "=r"(r[2]), "=r"(r[3]) : "r"(addr));
}
__device__ __forceinline__ void mma16816(float* c, const uint32_t* a, const uint32_t* b){
    asm volatile("mma.sync.aligned.m16n8k16.row.col.f32.f16.f16.f32 "
        "{%0,%1,%2,%3}, {%4,%5,%6,%7}, {%8,%9}, {%0,%1,%2,%3};"
        : "+f"(c[0]), "+f"(c[1]), "+f"(c[2]), "+f"(c[3])
        : "r"(a[0]), "r"(a[1]), "r"(a[2]), "r"(a[3]), "r"(b[0]), "r"(b[1]));
}
__device__ __forceinline__ void cpa16(uint32_t d, const void* s){
    asm volatile("cp.async.cg.shared.global [%0], [%1], 16;" :: "r"(d), "l"(s));
}
#define CP_COMMIT() asm volatile("cp.async.commit_group;" ::: "memory")
#define CP_WAIT0()  asm volatile("cp.async.wait_group 0;" ::: "memory")
#define CP_WAIT1()  asm volatile("cp.async.wait_group 1;" ::: "memory")

// ================= prep kernels =================
__global__ void pack_b_kernel(const float* __restrict__ Whh, const float* __restrict__ W2,
                              const float* __restrict__ Wih, const float* __restrict__ W1,
                              const float* __restrict__ bih, const float* __restrict__ bhh){
    int row = blockIdx.x, k = threadIdx.x, j = row*256 + k;
    float ws = (row < 1024) ? Whh[j] : W2[(size_t)(row-1024)*256 + k];
    float wp = (row < 1024) ? Wih[j] : W1[(size_t)(row-1024)*256 + k];
    split2(ws, g_bs0[j], g_bs1[j]);
    split2(wp, g_bp0[j], g_bp1[j]);
    if (row < 4) g_bias[j] = bih[j] + bhh[j];
}

// delta = 2.5 * sum|vt| * (absmax*2^-11 + 2^-10)
__global__ void vtsum_kernel(const float* __restrict__ vt){
    __shared__ float ws[8];
    int tid = threadIdx.x, lane = tid & 31, wid = tid >> 5;
    float v = fabsf(vt[tid]);
#pragma unroll
    for (int off = 16; off; off >>= 1) v += __shfl_xor_sync(0xffffffffu, v, off);
    if (lane == 0) ws[wid] = v;
    __syncthreads();
    if (tid == 0){
        float s = 0.f;
#pragma unroll
        for (int i = 0; i < 8; i++) s += ws[i];
        float am = __int_as_float(g_absmax);
        g_delta = 2.5f * s * (am * 4.8828125e-4f + 9.765625e-4f);
    }
}

// fused: split enc rows AND compute h0 = c0 = sum_s enc (enc read once)
__global__ void prep_kernel(const float* __restrict__ e0, const float* __restrict__ e1,
                            const float* __restrict__ e2){
    int r = blockIdx.x;                       // 0..9599
    int k = threadIdx.x;
    int t = r / NPT, n = r % NPT;
    const float* e = ((t==0)?e0:((t==1)?e1:e2)) + (size_t)n*(Ssz*256) + k;
    size_t wbase = ((size_t)t*ERT + (size_t)n*Ssz)*256 + k;
    float s = 0.f;
#pragma unroll 1
    for (int ss = 0; ss < Ssz; ss++){
        float v = e[ss*256];
        s += v;
        split2(v, g_es0[wbase + (size_t)ss*256], g_es1[wbase + (size_t)ss*256]);
    }
    g_c[r*256+k] = s;
    split2(s, g_h0s[r*256+k], g_h1s[r*256+k]);
}

// ================= emulated-fp32 GEMM via mma.sync fp16 (2-way split, 3 products) =================
// R12 schedule (proven): CTA tile 128x64, warp tile 32x32, 2-stage, K-chunk 64, 2 CTAs/SM.
#define ASTR   72
#define ATILE  (128*ASTR*2)
#define BTILE  (64*ASTR*2)
#define STAGE  (2*ATILE + 2*BTILE)
#define GSMEM  (2*STAGE)

__global__ __launch_bounds__(256, 2) void gemm_kernel(
    const __half* __restrict__ A0, const __half* __restrict__ A1,
    const __half* __restrict__ B0, const __half* __restrict__ B1,
    float* __restrict__ Cg, float* __restrict__ Cd, __half* __restrict__ Ch)
{
    extern __shared__ __half sh[];
    uint32_t sb = smem_u32(sh);

    const int tid = threadIdx.x, lane = tid & 31, w = tid >> 5;
    const int wm = w & 3, wn = w >> 2;
    const size_t m0 = (size_t)blockIdx.y * 128;
    const int n0 = blockIdx.x * 64;

    float acc0[2][4][4], acc1[2][4][4];
#pragma unroll
    for (int i = 0; i < 2; i++)
#pragma unroll
        for (int j = 0; j < 4; j++)
#pragma unroll
            for (int q = 0; q < 4; q++){ acc0[i][j][q] = 0.f; acc1[i][j][q] = 0.f; }

    const __half* Asrc[2] = { A0 + m0*256, A1 + m0*256 };
    const __half* Bsrc[2] = { B0 + (size_t)n0*256, B1 + (size_t)n0*256 };

    const int arow = wm*32 + (lane & 15);
    const int akof = (lane >> 4) * 8;
    const int brow = wn*32 + (lane & 7) + ((lane >> 4) << 3);
    const int bkof = ((lane >> 3) & 1) * 8;

    auto load_stage = [&](int c){
        uint32_t base = sb + (uint32_t)(c & 1)*STAGE;
#pragma unroll
        for (int t = 0; t < 2; t++){
            const __half* src = Asrc[t] + c*64;
#pragma unroll
            for (int i = 0; i < 4; i++){
                int id = tid + i*256, row = id >> 3, seg = id & 7;
                cpa16(base + t*ATILE + (uint32_t)(row*ASTR + seg*8)*2,
                      src + (size_t)row*256 + seg*8);
            }
        }
#pragma unroll
        for (int t = 0; t < 2; t++){
            const __half* src = Bsrc[t] + c*64;
#pragma unroll
            for (int i = 0; i < 2; i++){
                int id = tid + i*256, row = id >> 3, seg = id & 7;
                cpa16(base + 2*ATILE + t*BTILE + (uint32_t)(row*ASTR + seg*8)*2,
                      src + (size_t)row*256 + seg*8);
            }
        }
        CP_COMMIT();
    };

    load_stage(0);
#pragma unroll 1
    for (int c = 0; c < 4; c++){
        if (c + 1 < 4){ load_stage(c + 1); CP_WAIT1(); }
        else CP_WAIT0();
        __syncthreads();
        uint32_t base = sb + (uint32_t)(c & 1)*STAGE;
        uint32_t a0b = base, a1b = base + ATILE;
        uint32_t b0b = base + 2*ATILE, b1b = b0b + BTILE;
#pragma unroll
        for (int ks = 0; ks < 4; ks++){
            uint32_t b0f[4][2], b1f[4][2];
#pragma unroll
            for (int f2 = 0; f2 < 2; f2++){
                uint32_t off = (uint32_t)((brow + f2*16)*ASTR + ks*16 + bkof)*2;
                uint32_t r[4];
                ldsm4(r, b0b + off);
                b0f[f2*2][0] = r[0]; b0f[f2*2][1] = r[1];
                b0f[f2*2+1][0] = r[2]; b0f[f2*2+1][1] = r[3];
                ldsm4(r, b1b + off);
                b1f[f2*2][0] = r[0]; b1f[f2*2][1] = r[1];
                b1f[f2*2+1][0] = r[2]; b1f[f2*2+1][1] = r[3];
            }
#pragma unroll
            for (int fm = 0; fm < 2; fm++){
                uint32_t aoff = (uint32_t)((arow + fm*16)*ASTR + ks*16 + akof)*2;
                uint32_t a0f[4], a1f[4];
                ldsm4(a0f, a0b + aoff);
                ldsm4(a1f, a1b + aoff);
#pragma unroll
                for (int fn = 0; fn < 4; fn++){
                    mma16816(acc0[fm][fn], a0f, b0f[fn]);
                    mma16816(acc1[fm][fn], a0f, b1f[fn]);
                    mma16816(acc1[fm][fn], a1f, b0f[fn]);
                }
            }
        }
        __syncthreads();
    }

    const bool isg = (n0 < 1024);
    float* Cb = isg ? Cg : Cd;
    const int cw = isg ? 1024 : 256;
    const int col = (isg ? n0 : (n0 - 1024)) + wn*32 + 2*(lane & 3);
    float am = 0.f;
#pragma unroll
    for (int fm = 0; fm < 2; fm++){
        size_t mrow = m0 + wm*32 + fm*16 + (lane >> 2);
#pragma unroll
        for (int fn = 0; fn < 4; fn++){
            float2 r0 = make_float2(fmaf(acc1[fm][fn][0], RINV, acc0[fm][fn][0]),
                                    fmaf(acc1[fm][fn][1], RINV, acc0[fm][fn][1]));
            float2 r1 = make_float2(fmaf(acc1[fm][fn][2], RINV, acc0[fm][fn][2]),
                                    fmaf(acc1[fm][fn][3], RINV, acc0[fm][fn][3]));
            *(float2*)(Cb + mrow*cw     + col + fn*8) = r0;
            *(float2*)(Cb + (mrow+8)*cw + col + fn*8) = r1;
            if (!isg && Ch){
                *(__half2*)(Ch + mrow*256     + col + fn*8) = __floats2half2_rn(r0.x, r0.y);
                *(__half2*)(Ch + (mrow+8)*256 + col + fn*8) = __floats2half2_rn(r1.x, r1.y);
                am = fmaxf(am, fmaxf(fmaxf(fabsf(r0.x), fabsf(r0.y)),
                                     fmaxf(fabsf(r1.x), fabsf(r1.y))));
            }
        }
    }
    if (!isg && Ch){
#pragma unroll
        for (int off = 16; off; off >>= 1)
            am = fmaxf(am, __shfl_xor_sync(0xffffffffu, am, off));
        if (lane == 0) atomicMax(&g_absmax, __float_as_int(am));
    }
}

// ================= cell0: initial cell (x=0, no gather) =================
__global__ __launch_bounds__(256) void cell0_kernel(){
    int k = threadIdx.x;
#pragma unroll
    for (int rr = 0; rr < 4; rr++){
        int r = blockIdx.x*4 + rr;
        const float* g = g_graw + (size_t)r*1024;
        float i = fsig (g[k]     + g_bias[k]);
        float f = fsig (g[256+k] + g_bias[256+k]);
        float gv= ftanh(g[512+k] + g_bias[512+k]);
        float o = fsig (g[768+k] + g_bias[768+k]);
        float cn = fmaf(f, g_c[r*256+k], i*gv);
        g_c[r*256+k] = cn;
        split2(o * ftanh(cn), g_h0s[r*256+k], g_h1s[r*256+k]);
    }
}

// approx attention dot on fp16 et row (warp-collective; identical math to R16)
__device__ __forceinline__ float attn_dot_h(uint4 raw, const float* dec_s,
                                            const float* vt_s, int lane){
    __half2* hp = (__half2*)&raw;
    float2 e01 = __half22float2(hp[0]);
    float2 e23 = __half22float2(hp[1]);
    float2 e45 = __half22float2(hp[2]);
    float2 e67 = __half22float2(hp[3]);
    float4 d0 = *(const float4*)(&dec_s[8*lane]);
    float4 d1 = *(const float4*)(&dec_s[8*lane + 4]);
    float4 v0 = *(const float4*)(&vt_s[8*lane]);
    float4 v1 = *(const float4*)(&vt_s[8*lane + 4]);
    float p0 = htanh(e01.x + d0.x) * v0.x;
    float p1 = htanh(e01.y + d0.y) * v0.y;
    p0 = fmaf(htanh(e23.x + d0.z), v0.z, p0);
    p1 = fmaf(htanh(e23.y + d0.w), v0.w, p1);
    p0 = fmaf(htanh(e45.x + d1.x), v1.x, p0);
    p1 = fmaf(htanh(e45.y + d1.y), v1.y, p1);
    p0 = fmaf(htanh(e67.x + d1.z), v1.z, p0);
    p1 = fmaf(htanh(e67.y + d1.w), v1.w, p1);
    return p0 + p1;
}
// precise attention dot — EXACT R12 expression & order (certified refine path)
__device__ __forceinline__ float attn_dot_p(float4 e0, float4 e1,
                                            const float* dec_s, const float* vt_s, int lane){
    float4 d0 = *(const float4*)(&dec_s[4*lane]);
    float4 d1 = *(const float4*)(&dec_s[128 + 4*lane]);
    float4 v0 = *(const float4*)(&vt_s[4*lane]);
    float4 v1 = *(const float4*)(&vt_s[128 + 4*lane]);
    float p0 = ftanh(e0.x + d0.x) * v0.x;
    float p1 = ftanh(e0.y + d0.y) * v0.y;
    p0 = fmaf(ftanh(e0.z + d0.z), v0.z, p0);
    p1 = fmaf(ftanh(e0.w + d0.w), v0.w, p1);
    p0 = fmaf(ftanh(e1.x + d1.x), v1.x, p0);
    p1 = fmaf(ftanh(e1.y + d1.y), v1.y, p1);
    p0 = fmaf(ftanh(e1.z + d1.z), v1.z, p0);
    p1 = fmaf(ftanh(e1.w + d1.w), v1.w, p1);
    return p0 + p1;
}
__device__ __forceinline__ float wredu(float p){
#pragma unroll
    for (int off = 16; off; off >>= 1) p += __shfl_xor_sync(0xffffffffu, p, off);
    return p;
}

// ============ fused attention (2 rows/CTA) + certified refine + cell(step+1) ============
__global__ __launch_bounds__(256) void attn_cell_kernel(int step, int do_cell,
                                                        const float* __restrict__ vt,
                                                        float* __restrict__ out){
    __shared__ float dec_s[2][256], vt_s[256], u_s[2][52];
    __shared__ float maxA_sh[2];
    __shared__ int cnt_sh[2], cand_sh[2][52], idx_sh[2];
    int tid = threadIdx.x, wid = tid >> 5, lane = tid & 31;
    int half = wid >> 2, wid4 = wid & 3;      // 4 warps per row
    int r0 = blockIdx.x * 2;
    int r = r0 + half;
    int t = r / NPT, n = r % NPT;
    dec_s[0][tid] = g_dec[(size_t)r0*256 + tid];
    dec_s[1][tid] = g_dec[(size_t)(r0+1)*256 + tid];
    vt_s[tid]  = vt[tid];
    if (tid < 2) cnt_sh[tid] = 0;
    __syncthreads();

    const char* ebh = (const char*)(eth_ptr(t) + (size_t)n*Ssz*256);  // 512 B per s-row
    // approx pass: this row's 4 warps cover s = wid4 + 8j and +4 (pairs), tail 48+wid4
#pragma unroll 1
    for (int j = 0; j < 6; j++){
        int s = wid4 + 8*j;
        uint4 rA = *(const uint4*)(ebh + (size_t)s*512 + lane*16);
        uint4 rB = *(const uint4*)(ebh + (size_t)(s+4)*512 + lane*16);
        float pA = wredu(attn_dot_h(rA, dec_s[half], vt_s, lane));
        float pB = wredu(attn_dot_h(rB, dec_s[half], vt_s, lane));
        if (lane == 0){ u_s[half][s] = pA; u_s[half][s + 4] = pB; }
    }
    if (wid4 < 2){
        int s = 48 + wid4;
        uint4 rA = *(const uint4*)(ebh + (size_t)s*512 + lane*16);
        float p = wredu(attn_dot_h(rA, dec_s[half], vt_s, lane));
        if (lane == 0) u_s[half][s] = p;
    }
    __syncthreads();

    // approx max: warp 0 -> row 0, warp 4 -> row 1
    if (wid4 == 0){
        float ua = u_s[half][lane];
        float ub = (lane + 32 < Ssz) ? u_s[half][lane + 32] : -CUDART_INF_F;
        float bm = fmaxf(ua, ub);
#pragma unroll
        for (int off = 16; off; off >>= 1)
            bm = fmaxf(bm, __shfl_xor_sync(0xffffffffu, bm, off));
        if (lane == 0) maxA_sh[half] = bm;
    }
    __syncthreads();

    // candidate set (threads 0..49 -> row 0, 128..177 -> row 1)
    {
        int h2 = tid >> 7, s = tid & 127;
        if (s < Ssz && u_s[h2][s] >= maxA_sh[h2] - g_delta){
            int slot = atomicAdd(&cnt_sh[h2], 1);
            cand_sh[h2][slot] = s;
        }
    }
    __syncthreads();

    // precise recompute of candidates from fp32 et (exact path -> exact argmax)
    const float* eb = et_ptr(t) + (size_t)n*Ssz*256;
    int cnt = cnt_sh[half];
#pragma unroll 1
    for (int ci = wid4; ci < cnt; ci += 4){
        int s = cand_sh[half][ci];
        const float4* ep = (const float4*)(eb + (size_t)s*256);
        float4 e0 = ep[lane], e1 = ep[32 + lane];
        float p = wredu(attn_dot_p(e0, e1, dec_s[half], vt_s, lane));
        if (lane == 0) u_s[half][s] = p;
    }
    __syncthreads();

    // final argmax + softmax (warp 0 -> row 0, warp 4 -> row 1)
    if (wid4 == 0){
        float ua = u_s[half][lane];
        float ub = (lane + 32 < Ssz) ? u_s[half][lane + 32] : -CUDART_INF_F;
        float bm = ua; int bi = lane;
        if (ub > bm){ bm = ub; bi = lane + 32; }
#pragma unroll
        for (int off = 16; off; off >>= 1){
            float vm = __shfl_xor_sync(0xffffffffu, bm, off);
            int   vi = __shfl_xor_sync(0xffffffffu, bi, off);
            if (vm > bm || (vm == bm && vi < bi)){ bm = vm; bi = vi; }
        }
        float ea = __expf(ua - bm);
        float eb2 = (lane + 32 < Ssz) ? __expf(ub - bm) : 0.f;
        float sm = ea + eb2;
#pragma unroll
        for (int off = 16; off; off >>= 1) sm += __shfl_xor_sync(0xffffffffu, sm, off);
        float inv = 1.0f / sm;
        float* so = out + (size_t)t*8160000 + (size_t)n*2500 + step*50;
        so[lane] = ea * inv;
        if (lane + 32 < Ssz) so[lane + 32] = eb2 * inv;
        if (lane == 0){
            idx_sh[half] = bi;
            out[(size_t)t*8160000 + 8000000 + (size_t)n*50 + step] = (float)bi;
        }
    }
    __syncthreads();

    if (do_cell){
        int k = tid;
#pragma unroll
        for (int rr = 0; rr < 2; rr++){
            int r2 = r0 + rr;
            int t2 = r2 / NPT, n2 = r2 % NPT;
            const float* g = g_graw + (size_t)r2*1024;
            const float* ex = gx_ptr(t2) + (size_t)(n2*Ssz + idx_sh[rr])*1024;
            float i = fsig (g[k]     + ex[k]     + g_bias[k]);
            float f = fsig (g[256+k] + ex[256+k] + g_bias[256+k]);
            float gv= ftanh(g[512+k] + ex[512+k] + g_bias[512+k]);
            float o = fsig (g[768+k] + ex[768+k] + g_bias[768+k]);
            float cn = fmaf(f, g_c[r2*256+k], i*gv);
            g_c[r2*256+k] = cn;
            split2(o * ftanh(cn), g_h0s[r2*256+k], g_h1s[r2*256+k]);
        }
    }
}

// ================= launch =================
extern "C" void kernel_launch(void* const* d_in, const int* in_sizes, int n_in,
                              void* d_out, int out_size){
    const float* home = (const float*)d_in[0];
    const float* vis  = (const float*)d_in[1];
    const float* team = (const float*)d_in[2];
    const float* Wih  = (const float*)d_in[3];
    const float* Whh  = (const float*)d_in[4];
    const float* bih  = (const float*)d_in[5];
    const float* bhh  = (const float*)d_in[6];
    const float* W1   = (const float*)d_in[7];
    const float* W2   = (const float*)d_in[8];
    const float* vt   = (const float*)d_in[9];
    float* out = (float*)d_out;

    cudaFuncSetAttribute(gemm_kernel, cudaFuncAttributeMaxDynamicSharedMemorySize, GSMEM);

    pack_b_kernel<<<NB, 256>>>(Whh, W2, Wih, W1, bih, bhh);
    prep_kernel<<<NROW, 256>>>(home, vis, team);

    __half *es0, *es1, *bp0, *bp1, *bs0, *bs1, *h0, *h1, *eth0, *eth1, *eth2;
    float *gx0, *gx1, *gx2, *et0, *et1, *et2, *graw, *dec;
    cudaGetSymbolAddress((void**)&es0, g_es0);  cudaGetSymbolAddress((void**)&es1, g_es1);
    cudaGetSymbolAddress((void**)&bp0, g_bp0);  cudaGetSymbolAddress((void**)&bp1, g_bp1);
    cudaGetSymbolAddress((void**)&bs0, g_bs0);  cudaGetSymbolAddress((void**)&bs1, g_bs1);
    cudaGetSymbolAddress((void**)&h0,  g_h0s);  cudaGetSymbolAddress((void**)&h1,  g_h1s);
    cudaGetSymbolAddress((void**)&gx0, g_gx0);  cudaGetSymbolAddress((void**)&gx1, g_gx1);
    cudaGetSymbolAddress((void**)&gx2, g_gx2);
    cudaGetSymbolAddress((void**)&et0, g_et0);  cudaGetSymbolAddress((void**)&et1, g_et1);
    cudaGetSymbolAddress((void**)&et2, g_et2);
    cudaGetSymbolAddress((void**)&eth0, g_eth0); cudaGetSymbolAddress((void**)&eth1, g_eth1);
    cudaGetSymbolAddress((void**)&eth2, g_eth2);
    cudaGetSymbolAddress((void**)&graw, g_graw); cudaGetSymbolAddress((void**)&dec, g_dec);

    float* gxs[3] = {gx0, gx1, gx2};
    float* ets[3] = {et0, et1, et2};
    __half* eths[3] = {eth0, eth1, eth2};
    for (int t = 0; t < 3; t++){
        size_t off = (size_t)t * ERT * 256;
        gemm_kernel<<<dim3(20, 1250), 256, GSMEM>>>(es0 + off, es1 + off, bp0, bp1,
                                                    gxs[t], ets[t], eths[t]);
    }
    vtsum_kernel<<<1, 256>>>(vt);     // after et gemms: needs g_absmax

    // bootstrap: gates from h0 -> cell0 -> gates+dec
    gemm_kernel<<<dim3(20, 75), 256, GSMEM>>>(h0, h1, bs0, bs1, graw, dec, (__half*)0);
    cell0_kernel<<<NROW/4, 256>>>();
    gemm_kernel<<<dim3(20, 75), 256, GSMEM>>>(h0, h1, bs0, bs1, graw, dec, (__half*)0);

    for (int i = 0; i < Ssz; i++){
        attn_cell_kernel<<<NROW/2, 256>>>(i, (i + 1 < Ssz) ? 1 : 0, vt, out);
        if (i + 1 < Ssz)
            gemm_kernel<<<dim3(20, 75), 256, GSMEM>>>(h0, h1, bs0, bs1, graw, dec, (__half*)0);
    }
}